// round 1
// baseline (speedup 1.0000x reference)
#include <cuda_runtime.h>
#include <math.h>

#define SEQ    4096
#define DMODEL 1024
#define NH     16
#define HS     64

// Scratch (no cudaMalloc allowed): Q/K/V head-major [H][S][64], attn out [S][D]
__device__ float g_Q[NH * SEQ * HS];
__device__ float g_K[NH * SEQ * HS];
__device__ float g_V[NH * SEQ * HS];
__device__ float g_attn[SEQ * DMODEL];

// ---------------------------------------------------------------------------
// GEMM: C[M,N] = A[M,1024] * B[N,1024]^T + bias[N]
// MODE 0: A = x, scatter into g_Q/g_K/g_V (N = 3072)
// MODE 1: A = g_attn, write C = d_out   (N = 1024)
// 128x128 block, BK=16, 256 threads, 8x8 per-thread register tile.
// ---------------------------------------------------------------------------
template <int MODE>
__global__ __launch_bounds__(256) void gemm_bias_kernel(
    const float* __restrict__ A, const float* __restrict__ B,
    const float* __restrict__ bias, float* __restrict__ C)
{
    __shared__ float As[16][132];   // [k][m], padded
    __shared__ float Bs[16][132];   // [k][n], padded

    const int Kd = DMODEL;
    const int bm = blockIdx.y * 128;
    const int bn = blockIdx.x * 128;
    const int t  = threadIdx.x;
    const int tx = t & 15;          // -> cols tx*8 .. +7
    const int ty = t >> 4;          // -> rows ty*8 .. +7

    const float* __restrict__ Ap = (MODE == 0) ? A : g_attn;

    float acc[8][8];
#pragma unroll
    for (int i = 0; i < 8; i++)
#pragma unroll
        for (int j = 0; j < 8; j++) acc[i][j] = 0.f;

    const int r0 = t >> 2;          // rows 0..63
    const int g0 = (t & 3) * 4;     // k group 0/4/8/12
    const int r1 = r0 + 64;         // rows 64..127

    for (int k0 = 0; k0 < Kd; k0 += 16) {
        float4 a0 = *(const float4*)&Ap[(size_t)(bm + r0) * Kd + k0 + g0];
        float4 a1 = *(const float4*)&Ap[(size_t)(bm + r1) * Kd + k0 + g0];
        float4 b0 = *(const float4*)&B [(size_t)(bn + r0) * Kd + k0 + g0];
        float4 b1 = *(const float4*)&B [(size_t)(bn + r1) * Kd + k0 + g0];

        __syncthreads();   // previous compute done before overwrite
        As[g0+0][r0] = a0.x; As[g0+1][r0] = a0.y; As[g0+2][r0] = a0.z; As[g0+3][r0] = a0.w;
        As[g0+0][r1] = a1.x; As[g0+1][r1] = a1.y; As[g0+2][r1] = a1.z; As[g0+3][r1] = a1.w;
        Bs[g0+0][r0] = b0.x; Bs[g0+1][r0] = b0.y; Bs[g0+2][r0] = b0.z; Bs[g0+3][r0] = b0.w;
        Bs[g0+0][r1] = b1.x; Bs[g0+1][r1] = b1.y; Bs[g0+2][r1] = b1.z; Bs[g0+3][r1] = b1.w;
        __syncthreads();

#pragma unroll
        for (int kk = 0; kk < 16; kk++) {
            float ra[8], rb[8];
            *(float4*)&ra[0] = *(const float4*)&As[kk][ty * 8];
            *(float4*)&ra[4] = *(const float4*)&As[kk][ty * 8 + 4];
            *(float4*)&rb[0] = *(const float4*)&Bs[kk][tx * 8];
            *(float4*)&rb[4] = *(const float4*)&Bs[kk][tx * 8 + 4];
#pragma unroll
            for (int i = 0; i < 8; i++)
#pragma unroll
                for (int j = 0; j < 8; j++)
                    acc[i][j] = fmaf(ra[i], rb[j], acc[i][j]);
        }
    }

    if (MODE == 0) {
        // scatter QKV: n<1024 -> Q, <2048 -> K, else V ; head-major layout
#pragma unroll
        for (int i = 0; i < 8; i++) {
            int m = bm + ty * 8 + i;
#pragma unroll
            for (int j = 0; j < 8; j++) {
                int n = bn + tx * 8 + j;
                float v = acc[i][j] + bias[n];
                int sel = n >> 10;
                int nn  = n & 1023;
                float* dst = (sel == 0) ? g_Q : (sel == 1) ? g_K : g_V;
                dst[((size_t)(nn >> 6) * SEQ + m) * HS + (nn & 63)] = v;
            }
        }
    } else {
#pragma unroll
        for (int i = 0; i < 8; i++) {
            int m = bm + ty * 8 + i;
#pragma unroll
            for (int j = 0; j < 8; j += 4) {
                int n = bn + tx * 8 + j;
                float4 v;
                v.x = acc[i][j+0] + bias[n+0];
                v.y = acc[i][j+1] + bias[n+1];
                v.z = acc[i][j+2] + bias[n+2];
                v.w = acc[i][j+3] + bias[n+3];
                *(float4*)&C[(size_t)m * DMODEL + n] = v;
            }
        }
    }
}

// ---------------------------------------------------------------------------
// Flash attention, fp32, online softmax.
// Grid (S/64, NH). 256 threads. 64x64 score tile, 4x4 per-thread register
// tile; thread t: tx = t&15 -> cols tx*4.., ty = t>>4 -> rows ty*4..
// Row group of 16 threads = contiguous half-warp -> shfl_xor reductions.
// Mask applied as -inf BEFORE scale == reference (mask-then-scale).
// ---------------------------------------------------------------------------
#define QS_STRIDE 68
#define PS_STRIDE 65
#define ATTN_SMEM ((3 * 64 * QS_STRIDE + 64 * PS_STRIDE) * 4)

__global__ __launch_bounds__(256) void attn_kernel(const int* __restrict__ cmask)
{
    extern __shared__ float sm[];
    float* Qs = sm;                         // [k][m] stride 68 (transposed)
    float* Ks = Qs + 64 * QS_STRIDE;        // [k][n] stride 68 (transposed)
    float* Vs = Ks + 64 * QS_STRIDE;        // [j][d] stride 68
    float* Ps = Vs + 64 * QS_STRIDE;        // [j][r] stride 65

    const int h   = blockIdx.y;
    const int it  = blockIdx.x;
    const int qi0 = it * 64;
    const int t   = threadIdx.x;
    const int tx  = t & 15;
    const int ty  = t >> 4;
    const int causal = cmask ? cmask[0] : 1;

    // load Q tile transposed: Qs[k][m] = Q[qi0+m][k]
    {
        const int row = t >> 2;             // 0..63
        const int ks  = (t & 3) * 16;
        const float* src = g_Q + ((size_t)h * SEQ + qi0 + row) * HS + ks;
#pragma unroll
        for (int u = 0; u < 4; u++) {
            float4 v = *(const float4*)(src + u * 4);
            Qs[(ks + u*4 + 0) * QS_STRIDE + row] = v.x;
            Qs[(ks + u*4 + 1) * QS_STRIDE + row] = v.y;
            Qs[(ks + u*4 + 2) * QS_STRIDE + row] = v.z;
            Qs[(ks + u*4 + 3) * QS_STRIDE + row] = v.w;
        }
    }

    float m_i[4], l_i[4], o[4][4];
#pragma unroll
    for (int ri = 0; ri < 4; ri++) {
        m_i[ri] = -INFINITY;
        l_i[ri] = 0.f;
#pragma unroll
        for (int di = 0; di < 4; di++) o[ri][di] = 0.f;
    }

    const int jt_end = causal ? it : (SEQ / 64 - 1);
    for (int jt = 0; jt <= jt_end; jt++) {
        __syncthreads();   // previous iter's PV reads done
        {
            const int row = t >> 2;
            const int ks  = (t & 3) * 16;
            const float* ksrc = g_K + ((size_t)h * SEQ + jt * 64 + row) * HS + ks;
            const float* vsrc = g_V + ((size_t)h * SEQ + jt * 64 + row) * HS + ks;
#pragma unroll
            for (int u = 0; u < 4; u++) {
                float4 kv = *(const float4*)(ksrc + u * 4);
                Ks[(ks + u*4 + 0) * QS_STRIDE + row] = kv.x;
                Ks[(ks + u*4 + 1) * QS_STRIDE + row] = kv.y;
                Ks[(ks + u*4 + 2) * QS_STRIDE + row] = kv.z;
                Ks[(ks + u*4 + 3) * QS_STRIDE + row] = kv.w;
                float4 vv = *(const float4*)(vsrc + u * 4);
                *(float4*)&Vs[row * QS_STRIDE + ks + u * 4] = vv;
            }
        }
        __syncthreads();

        // scores: s[ri][ci] = sum_k Q[row][k] * K[col][k]
        float s[4][4];
#pragma unroll
        for (int ri = 0; ri < 4; ri++)
#pragma unroll
            for (int ci = 0; ci < 4; ci++) s[ri][ci] = 0.f;

#pragma unroll 16
        for (int k = 0; k < 64; k++) {
            float qv[4], kv[4];
            *(float4*)qv = *(const float4*)&Qs[k * QS_STRIDE + ty * 4];
            *(float4*)kv = *(const float4*)&Ks[k * QS_STRIDE + tx * 4];
#pragma unroll
            for (int ri = 0; ri < 4; ri++)
#pragma unroll
                for (int ci = 0; ci < 4; ci++)
                    s[ri][ci] = fmaf(qv[ri], kv[ci], s[ri][ci]);
        }

        const bool diag = causal && (jt == it);
#pragma unroll
        for (int ri = 0; ri < 4; ri++) {
            const int row = qi0 + ty * 4 + ri;
#pragma unroll
            for (int ci = 0; ci < 4; ci++) {
                s[ri][ci] *= 0.125f;   // 1/sqrt(64)
                if (diag && (jt * 64 + tx * 4 + ci) > row) s[ri][ci] = -INFINITY;
            }
        }

        // online softmax per row (16 threads per row, contiguous half-warp)
#pragma unroll
        for (int ri = 0; ri < 4; ri++) {
            float mx = fmaxf(fmaxf(s[ri][0], s[ri][1]), fmaxf(s[ri][2], s[ri][3]));
#pragma unroll
            for (int off = 1; off < 16; off <<= 1)
                mx = fmaxf(mx, __shfl_xor_sync(0xffffffffu, mx, off));
            const float mnew  = fmaxf(m_i[ri], mx);
            const float alpha = __expf(m_i[ri] - mnew);
            float rs = 0.f;
#pragma unroll
            for (int ci = 0; ci < 4; ci++) {
                s[ri][ci] = __expf(s[ri][ci] - mnew);
                rs += s[ri][ci];
            }
#pragma unroll
            for (int off = 1; off < 16; off <<= 1)
                rs += __shfl_xor_sync(0xffffffffu, rs, off);
            l_i[ri] = l_i[ri] * alpha + rs;
            m_i[ri] = mnew;
#pragma unroll
            for (int di = 0; di < 4; di++) o[ri][di] *= alpha;
        }

        // write P transposed: Ps[j][r]
#pragma unroll
        for (int ci = 0; ci < 4; ci++)
#pragma unroll
            for (int ri = 0; ri < 4; ri++)
                Ps[(tx * 4 + ci) * PS_STRIDE + ty * 4 + ri] = s[ri][ci];
        __syncthreads();

        // O += P * V
#pragma unroll 8
        for (int j = 0; j < 64; j++) {
            float pv[4];
#pragma unroll
            for (int ri = 0; ri < 4; ri++)
                pv[ri] = Ps[j * PS_STRIDE + ty * 4 + ri];
            float vv[4];
            *(float4*)vv = *(const float4*)&Vs[j * QS_STRIDE + tx * 4];
#pragma unroll
            for (int ri = 0; ri < 4; ri++)
#pragma unroll
                for (int di = 0; di < 4; di++)
                    o[ri][di] = fmaf(pv[ri], vv[di], o[ri][di]);
        }
    }

    // epilogue: normalize and write back to [S, D] layout (col = h*64 + d)
#pragma unroll
    for (int ri = 0; ri < 4; ri++) {
        const float inv = 1.f / l_i[ri];
        float4 v;
        v.x = o[ri][0] * inv; v.y = o[ri][1] * inv;
        v.z = o[ri][2] * inv; v.w = o[ri][3] * inv;
        *(float4*)&g_attn[(size_t)(qi0 + ty * 4 + ri) * DMODEL + h * HS + tx * 4] = v;
    }
}

// ---------------------------------------------------------------------------
extern "C" void kernel_launch(void* const* d_in, const int* in_sizes, int n_in,
                              void* d_out, int out_size)
{
    const float* x     = (const float*)d_in[0];
    const float* w_qkv = (const float*)d_in[1];
    const float* b_qkv = (const float*)d_in[2];
    const float* w_o   = (const float*)d_in[3];
    const float* b_o   = (const float*)d_in[4];
    const int*   cmask = (n_in > 5) ? (const int*)d_in[5] : nullptr;

    cudaFuncSetAttribute(attn_kernel,
                         cudaFuncAttributeMaxDynamicSharedMemorySize, ATTN_SMEM);

    // QKV projection + scatter: M=4096, N=3072
    gemm_bias_kernel<0><<<dim3(3072 / 128, SEQ / 128), 256>>>(x, w_qkv, b_qkv, nullptr);

    // attention: one block per (64-row q-tile, head)
    attn_kernel<<<dim3(SEQ / 64, NH), 256, ATTN_SMEM>>>(cmask);

    // output projection: M=4096, N=1024
    gemm_bias_kernel<1><<<dim3(DMODEL / 128, SEQ / 128), 256>>>(nullptr, w_o, b_o,
                                                                (float*)d_out);
}

// round 2
// speedup vs baseline: 3.3604x; 3.3604x over previous
#include <cuda_runtime.h>
#include <math.h>
#include <stdint.h>

#define SEQ    4096
#define DMODEL 1024
#define NH     16
#define HS     64

// Scratch (no cudaMalloc allowed)
__device__ float g_Q[NH * SEQ * HS];
__device__ float g_K[NH * SEQ * HS];
__device__ float g_V[NH * SEQ * HS];
__device__ float g_attn[SEQ * DMODEL];

__device__ __forceinline__ uint32_t f2tf32(float x) {
    uint32_t r;
    asm("cvt.rna.tf32.f32 %0, %1;" : "=r"(r) : "f"(x));
    return r;
}

__device__ __forceinline__ void mma8(float* c,
    uint32_t a0, uint32_t a1, uint32_t a2, uint32_t a3,
    uint32_t b0, uint32_t b1)
{
    asm volatile(
        "mma.sync.aligned.m16n8k8.row.col.f32.tf32.tf32.f32 "
        "{%0,%1,%2,%3},{%4,%5,%6,%7},{%8,%9},{%0,%1,%2,%3};"
        : "+f"(c[0]), "+f"(c[1]), "+f"(c[2]), "+f"(c[3])
        : "r"(a0), "r"(a1), "r"(a2), "r"(a3), "r"(b0), "r"(b1));
}

__device__ __forceinline__ uint32_t fu(float x) { return __float_as_uint(x); }

// ---------------------------------------------------------------------------
// tf32 tensor-core GEMM: C[M,N] = A[M,1024] * B[N,1024]^T + bias[N]
// MODE 0: A = x, scatter into g_Q/g_K/g_V (N = 3072)
// MODE 1: A = g_attn, write C = d_out   (N = 1024)
// 128x128 block, BK=32, 256 threads (8 warps, 2x4), warp tile 64x32.
// smem stride 36 (== 4 mod 8) -> tf32 fragment LDS is bank-conflict-free.
// ---------------------------------------------------------------------------
template <int MODE>
__global__ __launch_bounds__(256) void gemm_tc(
    const float* __restrict__ A, const float* __restrict__ B,
    const float* __restrict__ bias, float* __restrict__ C)
{
    __shared__ float As[128 * 36];
    __shared__ float Bs[128 * 36];

    const float* __restrict__ Ap = (MODE == 0) ? A : g_attn;
    const int bm = blockIdx.y * 128;
    const int bn = blockIdx.x * 128;
    const int t    = threadIdx.x;
    const int warp = t >> 5;
    const int lane = t & 31;
    const int wm = (warp >> 2) * 64;
    const int wn = (warp & 3) * 32;
    const int lr = lane >> 2;
    const int lc = lane & 3;

    float c[4][4][4];
#pragma unroll
    for (int mf = 0; mf < 4; mf++)
#pragma unroll
        for (int nf = 0; nf < 4; nf++)
#pragma unroll
            for (int r = 0; r < 4; r++) c[mf][nf][r] = 0.f;

    for (int k0 = 0; k0 < DMODEL; k0 += 32) {
        __syncthreads();
#pragma unroll
        for (int j = 0; j < 4; j++) {
            int idx = t + j * 256;           // float4 index within 128x32 tile
            int row = idx >> 3;
            int col = (idx & 7) * 4;
            float4 va = *(const float4*)(Ap + (size_t)(bm + row) * DMODEL + k0 + col);
            float4 vb = *(const float4*)(B  + (size_t)(bn + row) * DMODEL + k0 + col);
            float4 wa, wb;
            wa.x = __uint_as_float(f2tf32(va.x)); wa.y = __uint_as_float(f2tf32(va.y));
            wa.z = __uint_as_float(f2tf32(va.z)); wa.w = __uint_as_float(f2tf32(va.w));
            wb.x = __uint_as_float(f2tf32(vb.x)); wb.y = __uint_as_float(f2tf32(vb.y));
            wb.z = __uint_as_float(f2tf32(vb.z)); wb.w = __uint_as_float(f2tf32(vb.w));
            *(float4*)(As + row * 36 + col) = wa;
            *(float4*)(Bs + row * 36 + col) = wb;
        }
        __syncthreads();

#pragma unroll
        for (int kk = 0; kk < 32; kk += 8) {
            uint32_t a[4][4], b[4][2];
#pragma unroll
            for (int mf = 0; mf < 4; mf++) {
                int m0 = wm + mf * 16 + lr;
                a[mf][0] = fu(As[(m0    ) * 36 + kk + lc    ]);
                a[mf][1] = fu(As[(m0 + 8) * 36 + kk + lc    ]);
                a[mf][2] = fu(As[(m0    ) * 36 + kk + lc + 4]);
                a[mf][3] = fu(As[(m0 + 8) * 36 + kk + lc + 4]);
            }
#pragma unroll
            for (int nf = 0; nf < 4; nf++) {
                int n0 = wn + nf * 8 + lr;
                b[nf][0] = fu(Bs[n0 * 36 + kk + lc    ]);
                b[nf][1] = fu(Bs[n0 * 36 + kk + lc + 4]);
            }
#pragma unroll
            for (int mf = 0; mf < 4; mf++)
#pragma unroll
                for (int nf = 0; nf < 4; nf++)
                    mma8(c[mf][nf], a[mf][0], a[mf][1], a[mf][2], a[mf][3],
                         b[nf][0], b[nf][1]);
        }
    }

    // epilogue: bias + write (float2 per row-half)
#pragma unroll
    for (int mf = 0; mf < 4; mf++) {
#pragma unroll
        for (int nf = 0; nf < 4; nf++) {
            int n = bn + wn + nf * 8 + 2 * lc;
            float b0 = bias[n], b1 = bias[n + 1];
#pragma unroll
            for (int rh = 0; rh < 2; rh++) {
                int m = bm + wm + mf * 16 + lr + rh * 8;
                float2 v;
                v.x = c[mf][nf][rh * 2 + 0] + b0;
                v.y = c[mf][nf][rh * 2 + 1] + b1;
                if (MODE == 0) {
                    int sel = n >> 10;
                    int nn  = n & 1023;
                    float* dst = (sel == 0) ? g_Q : (sel == 1) ? g_K : g_V;
                    *(float2*)&dst[((size_t)(nn >> 6) * SEQ + m) * HS + (nn & 63)] = v;
                } else {
                    *(float2*)&C[(size_t)m * DMODEL + n] = v;
                }
            }
        }
    }
}

// ---------------------------------------------------------------------------
// tf32 tensor-core flash attention. Grid (S/64, NH), 128 threads (4 warps).
// Warp w owns q-rows [w*16, w*16+16). 64x64 KV tiles, online softmax on
// mma C-fragments (rows live in lane quads -> shfl_xor 1,2 reductions).
// ---------------------------------------------------------------------------
#define QSTR 68   // == 4 mod 32: conflict-free for A/B frag pattern (4m+k)
#define VSTR 72   // == 8 mod 32: conflict-free for V B-frag pattern (8k+n)
#define ATTN_SMEM ((3 * 64 * QSTR + 64 * VSTR) * 4)

template <int STR>
__device__ __forceinline__ void load_tile_tf32(float* dst, const float* src, int t)
{
#pragma unroll
    for (int j = 0; j < 8; j++) {
        int idx = t + j * 128;           // float4 index 0..1023
        int row = idx >> 4;
        int col = (idx & 15) * 4;
        float4 v = *(const float4*)(src + ((size_t)idx << 2));
        float4 w;
        w.x = __uint_as_float(f2tf32(v.x)); w.y = __uint_as_float(f2tf32(v.y));
        w.z = __uint_as_float(f2tf32(v.z)); w.w = __uint_as_float(f2tf32(v.w));
        *(float4*)(dst + row * STR + col) = w;
    }
}

__global__ __launch_bounds__(128) void attn_tc(const int* __restrict__ cmask)
{
    extern __shared__ float sm[];
    float* Qs = sm;                       // [64][QSTR]
    float* Ks = Qs + 64 * QSTR;           // [64][QSTR]
    float* Vs = Ks + 64 * QSTR;           // [64][VSTR]
    float* Ps = Vs + 64 * VSTR;           // [64][QSTR]

    const int h   = blockIdx.y;
    const int it  = gridDim.x - 1 - blockIdx.x;   // big tiles first (tail packing)
    const int qi0 = it * 64;
    const int t    = threadIdx.x;
    const int warp = t >> 5;
    const int lane = t & 31;
    const int lr = lane >> 2;
    const int lc = lane & 3;
    const int w16 = warp * 16;
    const int causal = cmask ? cmask[0] : 1;

    load_tile_tf32<QSTR>(Qs, g_Q + ((size_t)h * SEQ + qi0) * HS, t);

    float mrow0 = -INFINITY, mrow1 = -INFINITY, l0 = 0.f, l1 = 0.f;
    float O[8][4];
#pragma unroll
    for (int nf = 0; nf < 8; nf++)
#pragma unroll
        for (int r = 0; r < 4; r++) O[nf][r] = 0.f;

    const int jt_end = causal ? it : (SEQ / 64 - 1);
    for (int jt = 0; jt <= jt_end; jt++) {
        __syncthreads();                 // prev iter done with Ks/Vs/Ps
        load_tile_tf32<QSTR>(Ks, g_K + ((size_t)h * SEQ + jt * 64) * HS, t);
        load_tile_tf32<VSTR>(Vs, g_V + ((size_t)h * SEQ + jt * 64) * HS, t);
        __syncthreads();

        // ---- S = Q K^T (16x64 per warp) ----
        float c[8][4];
#pragma unroll
        for (int nf = 0; nf < 8; nf++)
#pragma unroll
            for (int r = 0; r < 4; r++) c[nf][r] = 0.f;

#pragma unroll
        for (int kk = 0; kk < HS; kk += 8) {
            uint32_t a0 = fu(Qs[(w16 + lr    ) * QSTR + kk + lc    ]);
            uint32_t a1 = fu(Qs[(w16 + lr + 8) * QSTR + kk + lc    ]);
            uint32_t a2 = fu(Qs[(w16 + lr    ) * QSTR + kk + lc + 4]);
            uint32_t a3 = fu(Qs[(w16 + lr + 8) * QSTR + kk + lc + 4]);
#pragma unroll
            for (int nf = 0; nf < 8; nf++) {
                uint32_t b0 = fu(Ks[(nf * 8 + lr) * QSTR + kk + lc    ]);
                uint32_t b1 = fu(Ks[(nf * 8 + lr) * QSTR + kk + lc + 4]);
                mma8(c[nf], a0, a1, a2, a3, b0, b1);
            }
        }

        // ---- mask + scale ----
        const bool diag = causal && (jt == it);
        const int row0 = qi0 + w16 + lr;
        const int row1 = row0 + 8;
#pragma unroll
        for (int nf = 0; nf < 8; nf++) {
            int col = jt * 64 + nf * 8 + 2 * lc;
            c[nf][0] *= 0.125f; c[nf][1] *= 0.125f;
            c[nf][2] *= 0.125f; c[nf][3] *= 0.125f;
            if (diag) {
                if (col     > row0) c[nf][0] = -INFINITY;
                if (col + 1 > row0) c[nf][1] = -INFINITY;
                if (col     > row1) c[nf][2] = -INFINITY;
                if (col + 1 > row1) c[nf][3] = -INFINITY;
            }
        }

        // ---- online softmax (rows shared by lane quads) ----
        float mx0 = -INFINITY, mx1 = -INFINITY;
#pragma unroll
        for (int nf = 0; nf < 8; nf++) {
            mx0 = fmaxf(mx0, fmaxf(c[nf][0], c[nf][1]));
            mx1 = fmaxf(mx1, fmaxf(c[nf][2], c[nf][3]));
        }
        mx0 = fmaxf(mx0, __shfl_xor_sync(0xffffffffu, mx0, 1));
        mx0 = fmaxf(mx0, __shfl_xor_sync(0xffffffffu, mx0, 2));
        mx1 = fmaxf(mx1, __shfl_xor_sync(0xffffffffu, mx1, 1));
        mx1 = fmaxf(mx1, __shfl_xor_sync(0xffffffffu, mx1, 2));

        const float mn0 = fmaxf(mrow0, mx0);
        const float mn1 = fmaxf(mrow1, mx1);
        const float al0 = __expf(mrow0 - mn0);
        const float al1 = __expf(mrow1 - mn1);
        float s0 = 0.f, s1 = 0.f;
#pragma unroll
        for (int nf = 0; nf < 8; nf++) {
            c[nf][0] = __expf(c[nf][0] - mn0); s0 += c[nf][0];
            c[nf][1] = __expf(c[nf][1] - mn0); s0 += c[nf][1];
            c[nf][2] = __expf(c[nf][2] - mn1); s1 += c[nf][2];
            c[nf][3] = __expf(c[nf][3] - mn1); s1 += c[nf][3];
        }
        s0 += __shfl_xor_sync(0xffffffffu, s0, 1);
        s0 += __shfl_xor_sync(0xffffffffu, s0, 2);
        s1 += __shfl_xor_sync(0xffffffffu, s1, 1);
        s1 += __shfl_xor_sync(0xffffffffu, s1, 2);
        l0 = l0 * al0 + s0;  l1 = l1 * al1 + s1;
        mrow0 = mn0;         mrow1 = mn1;
#pragma unroll
        for (int nf = 0; nf < 8; nf++) {
            O[nf][0] *= al0; O[nf][1] *= al0;
            O[nf][2] *= al1; O[nf][3] *= al1;
        }

        // ---- P -> smem (tf32), same-warp region only ----
#pragma unroll
        for (int nf = 0; nf < 8; nf++) {
            float2 p0, p1;
            p0.x = __uint_as_float(f2tf32(c[nf][0]));
            p0.y = __uint_as_float(f2tf32(c[nf][1]));
            p1.x = __uint_as_float(f2tf32(c[nf][2]));
            p1.y = __uint_as_float(f2tf32(c[nf][3]));
            *(float2*)&Ps[(w16 + lr    ) * QSTR + nf * 8 + 2 * lc] = p0;
            *(float2*)&Ps[(w16 + lr + 8) * QSTR + nf * 8 + 2 * lc] = p1;
        }
        __syncwarp();

        // ---- O += P V ----
#pragma unroll
        for (int kk = 0; kk < 64; kk += 8) {
            uint32_t a0 = fu(Ps[(w16 + lr    ) * QSTR + kk + lc    ]);
            uint32_t a1 = fu(Ps[(w16 + lr + 8) * QSTR + kk + lc    ]);
            uint32_t a2 = fu(Ps[(w16 + lr    ) * QSTR + kk + lc + 4]);
            uint32_t a3 = fu(Ps[(w16 + lr + 8) * QSTR + kk + lc + 4]);
#pragma unroll
            for (int nf = 0; nf < 8; nf++) {
                uint32_t b0 = fu(Vs[(kk + lc    ) * VSTR + nf * 8 + lr]);
                uint32_t b1 = fu(Vs[(kk + lc + 4) * VSTR + nf * 8 + lr]);
                mma8(O[nf], a0, a1, a2, a3, b0, b1);
            }
        }
    }

    // ---- epilogue: normalize, write to [S, D] (col = h*64 + d) ----
    const float inv0 = 1.f / l0;
    const float inv1 = 1.f / l1;
#pragma unroll
    for (int nf = 0; nf < 8; nf++) {
        int col = h * HS + nf * 8 + 2 * lc;
        float2 v0, v1;
        v0.x = O[nf][0] * inv0; v0.y = O[nf][1] * inv0;
        v1.x = O[nf][2] * inv1; v1.y = O[nf][3] * inv1;
        *(float2*)&g_attn[(size_t)(qi0 + w16 + lr    ) * DMODEL + col] = v0;
        *(float2*)&g_attn[(size_t)(qi0 + w16 + lr + 8) * DMODEL + col] = v1;
    }
}

// ---------------------------------------------------------------------------
extern "C" void kernel_launch(void* const* d_in, const int* in_sizes, int n_in,
                              void* d_out, int out_size)
{
    const float* x     = (const float*)d_in[0];
    const float* w_qkv = (const float*)d_in[1];
    const float* b_qkv = (const float*)d_in[2];
    const float* w_o   = (const float*)d_in[3];
    const float* b_o   = (const float*)d_in[4];
    const int*   cmask = (n_in > 5) ? (const int*)d_in[5] : nullptr;

    cudaFuncSetAttribute(attn_tc,
                         cudaFuncAttributeMaxDynamicSharedMemorySize, ATTN_SMEM);

    gemm_tc<0><<<dim3(3072 / 128, SEQ / 128), 256>>>(x, w_qkv, b_qkv, nullptr);
    attn_tc<<<dim3(SEQ / 64, NH), 128, ATTN_SMEM>>>(cmask);
    gemm_tc<1><<<dim3(DMODEL / 128, SEQ / 128), 256>>>(nullptr, w_o, b_o,
                                                       (float*)d_out);
}